// round 17
// baseline (speedup 1.0000x reference)
#include <cuda_runtime.h>
#include <cuda_fp16.h>
#include <cstdint>

#define B_    32
#define CIN   512
#define CI    256
#define NPIX  3136
#define EPSV  1e-5f

// ---------------- scratch (static device globals; no allocation) ----------------
__device__ __align__(128) __half d_XT16[(size_t)B_ * NPIX * CIN];   // [b][pix][512]  x^T fp16
__device__ __align__(128) __half d_GT  [(size_t)B_ * NPIX * CI];    // [b][pix][256]  g^T
__device__ __align__(128) __half d_TP  [(size_t)B_ * CIN * NPIX];   // [b][512][pix]  theta|phi (pix-contig)
__device__ __align__(128) __half d_F16 [(size_t)B_ * CI * CI];      // [b][256][256]
__device__ __align__(128) __half d_YT  [(size_t)B_ * NPIX * CI];    // [b][pix][256]  y^T
__device__ __align__(128) __half d_Wcat16[3 * CI * CIN];            // [768][512]
__device__ __align__(128) __half d_Wr16[CIN * CI];                  // [512][256]
__device__ __align__(128) float d_GP[(size_t)2 * B_ * CI * CI];     // G2 split-K partials
__device__ float d_Bcat[3 * CI];
__device__ float d_Sum[CIN];
__device__ float d_Sq [CIN];
__device__ float d_Scale[CIN];
__device__ float d_Shift[CIN];

// ================= PTX helpers (sm_75/80+-portable) =================
__device__ __forceinline__ uint32_t smem_u32(const void* p) {
    uint32_t a;
    asm("{ .reg .u64 t; cvta.to.shared.u64 t, %1; cvt.u32.u64 %0, t; }" : "=r"(a) : "l"(p));
    return a;
}
__device__ __forceinline__ void cp16(uint32_t d, const void* s, bool ok) {
    int sz = ok ? 16 : 0;
    asm volatile("cp.async.cg.shared.global [%0], [%1], 16, %2;" :: "r"(d), "l"(s), "r"(sz) : "memory");
}
__device__ __forceinline__ void cp_commit() { asm volatile("cp.async.commit_group;" ::: "memory"); }
__device__ __forceinline__ void cp_wait1()  { asm volatile("cp.async.wait_group 1;" ::: "memory"); }
__device__ __forceinline__ void ldm4(uint32_t* r, uint32_t a) {
    asm volatile("ldmatrix.sync.aligned.m8n8.x4.shared.b16 {%0,%1,%2,%3}, [%4];"
        : "=r"(r[0]), "=r"(r[1]), "=r"(r[2]), "=r"(r[3]) : "r"(a));
}
__device__ __forceinline__ void ldm2(uint32_t* r, uint32_t a) {
    asm volatile("ldmatrix.sync.aligned.m8n8.x2.shared.b16 {%0,%1}, [%2];"
        : "=r"(r[0]), "=r"(r[1]) : "r"(a));
}
__device__ __forceinline__ void mma16(float* c, const uint32_t* a, const uint32_t* b) {
    asm volatile(
        "mma.sync.aligned.m16n8k16.row.col.f32.f16.f16.f32 "
        "{%0,%1,%2,%3}, {%4,%5,%6,%7}, {%8,%9}, {%0,%1,%2,%3};"
        : "+f"(c[0]), "+f"(c[1]), "+f"(c[2]), "+f"(c[3])
        : "r"(a[0]), "r"(a[1]), "r"(a[2]), "r"(a[3]), "r"(b[0]), "r"(b[1]));
}

// ---------------- prep: weights -> fp16, bias concat, zero stats ----------------
__global__ void prep_w(const float* __restrict__ gw, const float* __restrict__ gb,
                       const float* __restrict__ tw, const float* __restrict__ tb,
                       const float* __restrict__ pw, const float* __restrict__ pb,
                       const float* __restrict__ ww)
{
    int i = blockIdx.x * 256 + threadIdx.x;
    const int per = CI * CIN;
    if (i < 3 * per) {
        int m = i / per, off = i - m * per;
        d_Wcat16[i] = __float2half((m == 0 ? tw : (m == 1 ? pw : gw))[off]);
    }
    if (i < CIN * CI) d_Wr16[i] = __float2half(ww[i]);
    if (i < CI)            d_Bcat[i] = tb[i];
    else if (i < 2 * CI)   d_Bcat[i] = pb[i - CI];
    else if (i < 3 * CI)   d_Bcat[i] = gb[i - 2 * CI];
    if (i < CIN) { d_Sum[i] = 0.f; d_Sq[i] = 0.f; }
}

// ---------------- x [b][512][3136] fp32 -> xT16 [b][3136][512] fp16 (64x64 tiles) ----
__global__ void xT_k(const float* __restrict__ x)
{
    __shared__ __half t[64][66];
    const int tid = threadIdx.x;
    const int p0 = blockIdx.x * 64, c0 = blockIdx.y * 64, b = blockIdx.z;
    const float* xb = x + (size_t)b * CIN * NPIX;
    #pragma unroll
    for (int ps = 0; ps < 4; ps++) {
        int ch = (tid >> 4) + ps * 16;
        int px = (tid & 15) * 4;
        float4 v = *(const float4*)(xb + (size_t)(c0 + ch) * NPIX + p0 + px);
        t[ch][px + 0] = __float2half(v.x);
        t[ch][px + 1] = __float2half(v.y);
        t[ch][px + 2] = __float2half(v.z);
        t[ch][px + 3] = __float2half(v.w);
    }
    __syncthreads();
    __half* o = d_XT16 + (size_t)b * NPIX * CIN;
    #pragma unroll
    for (int ps = 0; ps < 2; ps++) {
        int px = (tid >> 3) + ps * 32;
        int cc = (tid & 7) * 8;
        __half v[8];
        #pragma unroll
        for (int i = 0; i < 8; i++) v[i] = t[cc + i][px];
        *(uint4*)(o + (size_t)(p0 + px) * CIN + c0 + cc) = *(uint4*)v;
    }
}

// ================= fp16 mma.sync GEMM, 3-stage cp.async, KTILE=64 ================
// D[M, N] = alpha * A @ B^T ; A: [M,K] fp16 K-contig, B: [N,K] fp16 K-contig.
// OMODE 0: C fp16 [M][ldc] plain.
// OMODE 1: C fp32 [M][ldc] + per-row bias + residual + per-row BN stats (G4).
// OMODE 2: split-K fp32 partials into d_GP (G2).
// OMODE 3: G1 — rows=pix, cols=ch'[0..768): ch'<512 -> d_TP transposed; else d_GT.
// Block 128x128, 256 thr (8 warps, 2x4 grid of 64x32 tiles), KTILE=64 (4 k16 steps).
// Smem rows: 64 halves padded to 72 (36 words): ldmatrix octet banks 9r mod 8 = r
// (bijective), cp.async quarter-warp groups (1+c) mod 8 (bijective). 144B row aligned.
template<int OMODE, int SPLIT>
__global__ void __launch_bounds__(256, 2) gemm16(
    int Mtot, int Ntot, int KT, float alpha,
    const __half* __restrict__ A, int lda, long long sA,
    const __half* __restrict__ B, int ldb, long long sB,
    void* __restrict__ Cv, int ldc, long long sC,
    const float* __restrict__ bias,
    const float* __restrict__ res, long long sR)
{
    constexpr int AW = 128 * 36;                     // A words per stage (4608)
    constexpr int STG32 = 2 * AW;                    // 9216 u32 per stage (A+B)
    extern __shared__ uint32_t sm[];
    const uint32_t smb = smem_u32(sm);

    const int tid = threadIdx.x;
    int b = blockIdx.z, kt0 = 0, ktn = KT;
    float* partC = nullptr;
    if (SPLIT > 1) {
        b = blockIdx.z / SPLIT;
        int sp = blockIdx.z % SPLIT;
        int base = KT / SPLIT, rem = KT % SPLIT;
        kt0 = sp * base + (sp < rem ? sp : rem);
        ktn = base + (sp < rem ? 1 : 0);
        partC = d_GP + ((size_t)sp * B_ + b) * (CI * CI);
    }
    A += (long long)b * sA;
    B += (long long)b * sB;
    const int rowA = blockIdx.y * 128;
    const int colB = blockIdx.x * 128;
    const int warp = tid >> 5, lane = tid & 31;
    const int wr = warp >> 2, wc = warp & 3;         // 2x4 warp grid, 64x32 tiles
    const int g = lane >> 2, q = lane & 3;

    // ldmatrix per-thread address components (u32-word units within a stage)
    const int arow = wr * 64 + (lane & 7) + ((lane >> 3) & 1) * 8;  // + mt*16
    const int ah4  = ((lane >> 4) & 1) * 4;
    const int l15  = lane & 15;
    const int brow = wc * 32 + (l15 & 7);                            // + nt*8
    const int bh4  = (l15 >> 3) * 4;

    float acc[4][4][4];
    #pragma unroll
    for (int i = 0; i < 4; i++)
        #pragma unroll
        for (int j = 0; j < 4; j++)
            #pragma unroll
            for (int k = 0; k < 4; k++) acc[i][j][k] = 0.f;

    auto load_tile = [&](int s, int kt) {
        const uint32_t baseA = smb + (uint32_t)(s * STG32) * 4;
        #pragma unroll
        for (int j = 0; j < 4; j++) {                // A: 1024 16B chunks (8/row)
            int u = tid + j * 256;
            int row = u >> 3, c = u & 7;
            bool ok = rowA + row < Mtot;
            cp16(baseA + (uint32_t)(row * 36 + c * 4) * 4,
                 A + (size_t)(ok ? rowA + row : 0) * lda + kt * 64 + c * 8, ok);
        }
        const uint32_t baseB = baseA + AW * 4;
        #pragma unroll
        for (int j = 0; j < 4; j++) {                // B: 1024 16B chunks
            int u = tid + j * 256;
            int row = u >> 3, c = u & 7;
            bool ok = colB + row < Ntot;
            cp16(baseB + (uint32_t)(row * 36 + c * 4) * 4,
                 B + (size_t)(ok ? colB + row : 0) * ldb + kt * 64 + c * 8, ok);
        }
        cp_commit();
    };

    auto compute = [&](int s) {
        const uint32_t stage = smb + (uint32_t)(s * STG32) * 4;
        const uint32_t aBase = stage + (uint32_t)(arow * 36 + ah4) * 4;
        const uint32_t bBase = stage + AW * 4 + (uint32_t)(brow * 36 + bh4) * 4;
        #pragma unroll
        for (int k16 = 0; k16 < 4; k16++) {
            uint32_t af[4][4], bf[4][2];
            #pragma unroll
            for (int mt = 0; mt < 4; mt++)
                ldm4(af[mt], aBase + (uint32_t)(mt * 2304 + k16 * 32));
            #pragma unroll
            for (int nt = 0; nt < 4; nt++)
                ldm2(bf[nt], bBase + (uint32_t)(nt * 1152 + k16 * 32));
            #pragma unroll
            for (int mt = 0; mt < 4; mt++)
                #pragma unroll
                for (int nt = 0; nt < 4; nt++)
                    mma16(acc[mt][nt], af[mt], bf[nt]);
        }
    };

    // prologue: local tiles 0,1 (all KT chunks are >= 2)
    load_tile(0, kt0);
    load_tile(1, kt0 + 1);

    for (int lt = 0; lt < ktn; lt++) {
        cp_wait1();                                  // local tile lt resident
        __syncthreads();
        int nt = lt + 2;
        if (nt < ktn) load_tile(nt % 3, kt0 + nt);
        else cp_commit();                            // keep group count uniform
        compute(lt % 3);
    }

    // ---------------- epilogue ----------------
    if (OMODE == 0) {
        __half* C = ((__half*)Cv) + (long long)b * sC;
        #pragma unroll
        for (int mt = 0; mt < 4; mt++) {
            const int r0 = rowA + wr * 64 + mt * 16 + g;
            const int r1 = r0 + 8;
            #pragma unroll
            for (int nt = 0; nt < 4; nt++) {
                const int col = colB + wc * 32 + nt * 8 + 2 * q;
                if (col >= Ntot) continue;
                float v0 = acc[mt][nt][0] * alpha;
                float v1 = acc[mt][nt][1] * alpha;
                float v2 = acc[mt][nt][2] * alpha;
                float v3 = acc[mt][nt][3] * alpha;
                if (r0 < Mtot) *(__half2*)(C + (size_t)r0 * ldc + col) = __floats2half2_rn(v0, v1);
                if (r1 < Mtot) *(__half2*)(C + (size_t)r1 * ldc + col) = __floats2half2_rn(v2, v3);
            }
        }
    } else if (OMODE == 3) {
        // G1: rows = pix, cols = ch' in [0,768). Block-uniform split at 512.
        __half* TPb = d_TP + (size_t)b * ((size_t)CIN * NPIX);
        __half* GTb = d_GT + (size_t)b * ((size_t)NPIX * CI);
        #pragma unroll
        for (int mt = 0; mt < 4; mt++) {
            const int r0 = rowA + wr * 64 + mt * 16 + g;
            const int r1 = r0 + 8;
            #pragma unroll
            for (int nt = 0; nt < 4; nt++) {
                const int col = colB + wc * 32 + nt * 8 + 2 * q;
                float v0 = acc[mt][nt][0] + bias[col];
                float v1 = acc[mt][nt][1] + bias[col + 1];
                float v2 = acc[mt][nt][2] + bias[col];
                float v3 = acc[mt][nt][3] + bias[col + 1];
                if (colB < 512) {                    // theta|phi -> TP[ch][pix]
                    if (r0 < Mtot) {
                        TPb[(size_t)col * NPIX + r0]       = __float2half_rn(v0);
                        TPb[(size_t)(col + 1) * NPIX + r0] = __float2half_rn(v1);
                    }
                    if (r1 < Mtot) {
                        TPb[(size_t)col * NPIX + r1]       = __float2half_rn(v2);
                        TPb[(size_t)(col + 1) * NPIX + r1] = __float2half_rn(v3);
                    }
                } else {                             // g -> GT[pix][ch-512]
                    const int gc = col - 512;
                    if (r0 < Mtot) *(__half2*)(GTb + (size_t)r0 * CI + gc) = __floats2half2_rn(v0, v1);
                    if (r1 < Mtot) *(__half2*)(GTb + (size_t)r1 * CI + gc) = __floats2half2_rn(v2, v3);
                }
            }
        }
    } else if (OMODE == 2) {
        // split-K fp32 partial store
        float* C = partC;
        #pragma unroll
        for (int mt = 0; mt < 4; mt++) {
            const int r0 = rowA + wr * 64 + mt * 16 + g;
            const int r1 = r0 + 8;
            #pragma unroll
            for (int nt = 0; nt < 4; nt++) {
                const int col = colB + wc * 32 + nt * 8 + 2 * q;
                if (col < Ntot) {
                    if (r0 < Mtot)
                        *(float2*)(C + (size_t)r0 * ldc + col) =
                            make_float2(acc[mt][nt][0] * alpha, acc[mt][nt][1] * alpha);
                    if (r1 < Mtot)
                        *(float2*)(C + (size_t)r1 * ldc + col) =
                            make_float2(acc[mt][nt][2] * alpha, acc[mt][nt][3] * alpha);
                }
            }
        }
    } else {
        // G4: row-major fp32 out + per-row bias + residual + per-row BN stats
        float* C = ((float*)Cv) + (long long)b * sC;
        const float* R = res + (long long)b * sR;
        float sumr[8], sqr[8];
        #pragma unroll
        for (int i = 0; i < 8; i++) { sumr[i] = 0.f; sqr[i] = 0.f; }

        #pragma unroll
        for (int mt = 0; mt < 4; mt++) {
            const int r0 = rowA + wr * 64 + mt * 16 + g;
            const int r1 = r0 + 8;
            const float bv0 = bias[r0];
            const float bv1 = bias[r1];
            float* c0p = C + (size_t)r0 * ldc;
            float* c1p = C + (size_t)r1 * ldc;
            const float* rr0 = R + (size_t)r0 * ldc;
            const float* rr1 = R + (size_t)r1 * ldc;
            #pragma unroll
            for (int nt = 0; nt < 4; nt++) {
                const int col = colB + wc * 32 + nt * 8 + 2 * q;
                if (col < Ntot) {
                    float2 e0 = *(const float2*)(rr0 + col);
                    float2 e1 = *(const float2*)(rr1 + col);
                    float v0 = acc[mt][nt][0] + bv0 + e0.x;
                    float v1 = acc[mt][nt][1] + bv0 + e0.y;
                    float v2 = acc[mt][nt][2] + bv1 + e1.x;
                    float v3 = acc[mt][nt][3] + bv1 + e1.y;
                    *(float2*)(c0p + col) = make_float2(v0, v1);
                    *(float2*)(c1p + col) = make_float2(v2, v3);
                    sumr[2 * mt]     += v0 + v1;
                    sqr [2 * mt]     += v0 * v0 + v1 * v1;
                    sumr[2 * mt + 1] += v2 + v3;
                    sqr [2 * mt + 1] += v2 * v2 + v3 * v3;
                }
            }
        }
        __syncthreads();
        float* sred = (float*)sm;
        if (tid < 128) { sred[tid] = 0.f; sred[128 + tid] = 0.f; }
        __syncthreads();
        #pragma unroll
        for (int i = 0; i < 8; i++) {
            int lr = wr * 64 + (i >> 1) * 16 + g + (i & 1) * 8;
            atomicAdd(&sred[lr], sumr[i]);
            atomicAdd(&sred[128 + lr], sqr[i]);
        }
        __syncthreads();
        if (tid < 128) {
            atomicAdd(&d_Sum[rowA + tid], sred[tid]);
            atomicAdd(&d_Sq [rowA + tid], sred[128 + tid]);
        }
    }
}

// ---------------- reduce G2 partials (2-way) -> d_F16 ----------------
__global__ void reduce_f_k()
{
    const size_t per = (size_t)B_ * CI * CI;
    size_t gid = (size_t)blockIdx.x * 256 + threadIdx.x;
    size_t i4 = gid * 4;
    if (i4 >= per) return;
    float4 s0 = *(const float4*)(d_GP + i4);
    float4 s1 = *(const float4*)(d_GP + per + i4);
    *(__half2*)(d_F16 + i4)     = __floats2half2_rn(s0.x + s1.x, s0.y + s1.y);
    *(__half2*)(d_F16 + i4 + 2) = __floats2half2_rn(s0.z + s1.z, s0.w + s1.w);
}

// ---------------- BN finalize / apply ----------------
__global__ void finalize_k(const float* __restrict__ gamma, const float* __restrict__ beta)
{
    int c = threadIdx.x;
    if (c < CIN) {
        const float cnt = (float)((long long)B_ * NPIX);
        float mean = d_Sum[c] / cnt;
        float var  = d_Sq[c] / cnt - mean * mean;
        float s = gamma[c] * rsqrtf(var + EPSV);
        d_Scale[c] = s;
        d_Shift[c] = beta[c] - mean * s;
    }
}

__global__ void apply_k(float* __restrict__ out)
{
    const long long n4 = (long long)B_ * CIN * NPIX / 4;
    const long long stride = (long long)gridDim.x * blockDim.x;
    for (long long i = (long long)blockIdx.x * blockDim.x + threadIdx.x; i < n4; i += stride) {
        int c = (int)((i / (NPIX / 4)) % CIN);
        float s = d_Scale[c], sh = d_Shift[c];
        float4 v = ((float4*)out)[i];
        v.x = v.x * s + sh; v.y = v.y * s + sh;
        v.z = v.z * s + sh; v.w = v.w * s + sh;
        ((float4*)out)[i] = v;
    }
}

// ---------------- launch ----------------
extern "C" void kernel_launch(void* const* d_in, const int* in_sizes, int n_in,
                              void* d_out, int out_size)
{
    const float* x       = (const float*)d_in[0];
    const float* g_w     = (const float*)d_in[1];
    const float* g_b     = (const float*)d_in[2];
    const float* theta_w = (const float*)d_in[3];
    const float* theta_b = (const float*)d_in[4];
    const float* phi_w   = (const float*)d_in[5];
    const float* phi_b   = (const float*)d_in[6];
    const float* W_w     = (const float*)d_in[7];
    const float* W_b     = (const float*)d_in[8];
    const float* gamma   = (const float*)d_in[9];
    const float* beta    = (const float*)d_in[10];
    float* out = (float*)d_out;

    __half *xt, *gt, *tp, *f16, *yt, *wc16, *wr16;
    float *bcat;
    cudaGetSymbolAddress((void**)&xt,   d_XT16);
    cudaGetSymbolAddress((void**)&gt,   d_GT);
    cudaGetSymbolAddress((void**)&tp,   d_TP);
    cudaGetSymbolAddress((void**)&f16,  d_F16);
    cudaGetSymbolAddress((void**)&yt,   d_YT);
    cudaGetSymbolAddress((void**)&wc16, d_Wcat16);
    cudaGetSymbolAddress((void**)&wr16, d_Wr16);
    cudaGetSymbolAddress((void**)&bcat, d_Bcat);

    constexpr int SMEM = 3 * 9216 * 4;               // 110592 B (x2 CTA = 221184 <= 228KB)
    cudaFuncSetAttribute(gemm16<3, 1>, cudaFuncAttributeMaxDynamicSharedMemorySize, SMEM);
    cudaFuncSetAttribute(gemm16<2, 2>, cudaFuncAttributeMaxDynamicSharedMemorySize, SMEM);
    cudaFuncSetAttribute(gemm16<0, 1>, cudaFuncAttributeMaxDynamicSharedMemorySize, SMEM);
    cudaFuncSetAttribute(gemm16<1, 1>, cudaFuncAttributeMaxDynamicSharedMemorySize, SMEM);

    const long long sX   = (long long)CIN * NPIX;       // x / out per batch
    const long long sXT  = (long long)NPIX * CIN;
    const long long sGT  = (long long)NPIX * CI;
    const long long sTP  = (long long)CIN * NPIX;
    const long long sF   = (long long)CI * CI;
    const long long sYT  = (long long)NPIX * CI;

    // 0) prep weights + x transpose
    prep_w<<<1536, 256>>>(g_w, g_b, theta_w, theta_b, phi_w, phi_b, W_w);
    xT_k<<<dim3(49, 8, B_), 256>>>(x);

    // 1) G1: xT16 @ Wcat^T + Bcat -> theta|phi into TP[ch][pix], g into GT[pix][256]
    gemm16<3, 1><<<dim3(6, 25, B_), 256, SMEM>>>(
        NPIX, 3 * CI, CIN / 64, 1.f,
        xt, CIN, sXT,
        wc16, CIN, 0,
        nullptr, 0, 0,
        bcat, nullptr, 0);

    // 2) split-K(2) gram: partials[sp][b] = theta @ phi^T / N over K chunk sp
    gemm16<2, 2><<<dim3(2, 2, B_ * 2), 256, SMEM>>>(
        CI, CI, NPIX / 64, 1.f / (float)NPIX,
        tp, NPIX, sTP,
        tp + (long long)CI * NPIX, NPIX, sTP,
        nullptr, CI, sF,
        nullptr, nullptr, 0);

    // 2b) reduce partials -> f16
    reduce_f_k<<<(B_ * CI * CI / 4 + 255) / 256, 256>>>();

    // 3) yT[pix][c] = GT[pix][256k] @ f[c][256k]^T
    gemm16<0, 1><<<dim3(2, 25, B_), 256, SMEM>>>(
        NPIX, CI, CI / 64, 1.f,
        gt, CI, sGT,
        f16, CI, sF,
        yt, CI, sYT,
        nullptr, nullptr, 0);

    // 4) z[ch][pix] = Wr16[512ch][256k] @ yT[pix][256k]^T + W_b[ch] + x  (row stats)
    gemm16<1, 1><<<dim3(25, 4, B_), 256, SMEM>>>(
        CIN, NPIX, CI / 64, 1.f,
        wr16, CI, 0,
        yt, CI, sYT,
        out, NPIX, sX,
        W_b, x, sX);

    // 5) BN finalize + apply
    finalize_k<<<1, 512>>>(gamma, beta);
    apply_k<<<2368, 256>>>(out);
}